// round 12
// baseline (speedup 1.0000x reference)
#include <cuda_runtime.h>
#include <cuda_fp16.h>
#include <cstdint>

// VQ nearest-codebook lookup via 3-term FP16 mma.sync distance GEMM.
// R12: warp tile 64x64 (4 warps, 128 threads, 2m x 2n), 2 CTAs/SM.
// LDSM bytes per mma cut 1.5x vs 32x64 warp tile (shared pipe was the limiter).
//   z_e_x: [16,2048,256] f32 -> N=32768 rows, D=256
//   embedding: [1024,256] f32 -> K=1024 codes
// d_out (f32): z_q_x [N*D] @0, z_q_x_bar [N*D] @8388608, indices [N] @16777216
// argmax_k(x.c - ||c||^2/2); x = xh + xl (fp16 split), keep hh + hl + lh.

#define NTOK   32768
#define DDIM   256
#define KCODE  1024
#define BM     128
#define BN     128
#define KS     32              // k per stage (two k16 chunks)
#define NTILE  8
#define NG     64              // NTILE * (DDIM/KS)
#define PITCHH 40              // halves per row (80B pitch, ldsm conflict-free)

#define OUT_BAR   8388608
#define OUT_IDX  16777216

#define MAT_H   (BM * PITCHH)        // 5120 halves per matrix-stage
// half-index offsets: AH[buf]=buf*MAT_H, AL=(2+buf), BH=(4+buf), BL=(6+buf)
#define CN_F    (4 * MAT_H)          // float index after 8*MAT_H halves
#define DYN_SMEM (CN_F * 4 + KCODE * 4)   // 81920 + 4096 = 86016 B

__device__ float g_cnorm[KCODE];

// ---------------------------------------------------------------------------
__device__ __forceinline__ uint32_t smem_u32(const void* p) {
    uint32_t a;
    asm("{ .reg .u64 t; cvta.to.shared.u64 t, %1; cvt.u32.u64 %0, t; }"
        : "=r"(a) : "l"(p));
    return a;
}
#define LDSM4(r, addr) \
    asm volatile("ldmatrix.sync.aligned.m8n8.x4.shared.b16 {%0,%1,%2,%3}, [%4];" \
        : "=r"((r)[0]), "=r"((r)[1]), "=r"((r)[2]), "=r"((r)[3]) : "r"(addr))

__device__ __forceinline__ void mma_f16(float* c, const uint32_t* a,
                                        uint32_t b0, uint32_t b1) {
    asm volatile(
        "mma.sync.aligned.m16n8k16.row.col.f32.f16.f16.f32 "
        "{%0,%1,%2,%3}, {%4,%5,%6,%7}, {%8,%9}, {%0,%1,%2,%3};"
        : "+f"(c[0]), "+f"(c[1]), "+f"(c[2]), "+f"(c[3])
        : "r"(a[0]), "r"(a[1]), "r"(a[2]), "r"(a[3]), "r"(b0), "r"(b1));
}

__device__ __forceinline__ uint32_t h2u(__half2 v) {
    return *reinterpret_cast<uint32_t*>(&v);
}

__device__ __forceinline__ void split_f4(float4 v, uint2& h, uint2& l) {
    __half2 h01 = __floats2half2_rn(v.x, v.y);
    __half2 h23 = __floats2half2_rn(v.z, v.w);
    float2 f01 = __half22float2(h01);
    float2 f23 = __half22float2(h23);
    __half2 l01 = __floats2half2_rn(v.x - f01.x, v.y - f01.y);
    __half2 l23 = __floats2half2_rn(v.z - f23.x, v.w - f23.y);
    h.x = h2u(h01); h.y = h2u(h23);
    l.x = h2u(l01); l.y = h2u(l23);
}

__device__ __forceinline__ void split2_f4(float4 a, float4 b, uint4& h, uint4& l) {
    uint2 ha, la, hb, lb;
    split_f4(a, ha, la);
    split_f4(b, hb, lb);
    h.x = ha.x; h.y = ha.y; h.z = hb.x; h.w = hb.y;
    l.x = la.x; l.y = la.y; l.z = lb.x; l.w = lb.y;
}

// ---------------------------------------------------------------------------
__global__ void cnorm_kernel(const float* __restrict__ emb) {
    int warp = (blockIdx.x * blockDim.x + threadIdx.x) >> 5;
    int lane = threadIdx.x & 31;
    if (warp >= KCODE) return;
    const float* row = emb + (size_t)warp * DDIM;
    float s = 0.f;
    #pragma unroll
    for (int k = lane; k < DDIM; k += 32) { float v = row[k]; s += v * v; }
    #pragma unroll
    for (int o = 16; o; o >>= 1) s += __shfl_xor_sync(0xffffffffu, s, o);
    if (lane == 0) g_cnorm[warp] = s;
}

// ---------------------------------------------------------------------------
// 128 threads = 4 warps in 2(m) x 2(n); warp tile 64 rows x 64 codes.
// ---------------------------------------------------------------------------
__global__ __launch_bounds__(128, 2)
void vq_mma_kernel(const float* __restrict__ x,
                   const float* __restrict__ emb,
                   float* __restrict__ out) {
    extern __shared__ float dsm[];
    __half* hsm = (__half*)dsm;
    __shared__ float sV[2][BM];
    __shared__ int   sI[2][BM];
    __shared__ int   bidx_s[BM];

    const int tid = threadIdx.x;
    const int wid = tid >> 5;
    const int L   = tid & 31;
    const int rowBase = blockIdx.x * BM;
    const int mbase = (wid >> 1) * 64;       // 0/64
    const int nbase = (wid & 1) * 64;        // 0/64

    const uint32_t SB = smem_u32(dsm);

    // ldmatrix lane geometry (byte offsets inside a matrix-stage; 80B pitch)
    const int aRow = (L & 7) + 8 * ((L >> 3) & 1);
    const int aK   = (L >> 4) * 16;
    const uint32_t aBase = (uint32_t)((mbase + aRow) * 80 + aK);
    const uint32_t bBase = (uint32_t)((nbase + aRow) * 80 + aK);

    // cnorm table into smem (once)
    #pragma unroll
    for (int i = 0; i < 8; ++i) dsm[CN_F + tid + 128 * i] = g_cnorm[tid + 128 * i];

    float bV[8];
    int   bI[8];
    #pragma unroll
    for (int i = 0; i < 8; ++i) { bV[i] = -3.4e38f; bI[i] = 0x7fffffff; }

    float4 vS[4];

    // loader: thread owns row tid of both A and B; chunk = 16 floats
    #define LOAD_X(sidx, chunk) do { \
        const float* _p = x + (size_t)(rowBase + tid) * DDIM \
                        + ((sidx) & 7) * KS + (chunk) * 16; \
        vS[0] = ((const float4*)_p)[0]; vS[1] = ((const float4*)_p)[1]; \
        vS[2] = ((const float4*)_p)[2]; vS[3] = ((const float4*)_p)[3]; \
    } while (0)

    #define LOAD_C(sidx, chunk) do { \
        const float* _p = emb + (size_t)(((sidx) >> 3) * BN + tid) * DDIM \
                        + ((sidx) & 7) * KS + (chunk) * 16; \
        vS[0] = ((const float4*)_p)[0]; vS[1] = ((const float4*)_p)[1]; \
        vS[2] = ((const float4*)_p)[2]; vS[3] = ((const float4*)_p)[3]; \
    } while (0)

    #define STORE_CHUNK(hiOff, loOff, chunk) do { \
        const int _hb = tid * PITCHH + (chunk) * 16; \
        uint4 _h0, _l0, _h1, _l1; \
        split2_f4(vS[0], vS[1], _h0, _l0); \
        split2_f4(vS[2], vS[3], _h1, _l1); \
        *(uint4*)&hsm[(hiOff) + _hb]     = _h0; \
        *(uint4*)&hsm[(hiOff) + _hb + 8] = _h1; \
        *(uint4*)&hsm[(loOff) + _hb]     = _l0; \
        *(uint4*)&hsm[(loOff) + _hb + 8] = _l1; \
    } while (0)

    #define MMA_GROUP(afr, bfr) do { \
        _Pragma("unroll") \
        for (int _f = 0; _f < 4; ++_f) \
            _Pragma("unroll") \
            for (int _q = 0; _q < 4; ++_q) { \
                mma_f16(acc[_f][2 * _q],     (afr)[_f], (bfr)[_q][0], (bfr)[_q][2]); \
                mma_f16(acc[_f][2 * _q + 1], (afr)[_f], (bfr)[_q][1], (bfr)[_q][3]); \
            } \
    } while (0)

    float acc[4][8][4];
    #pragma unroll
    for (int f = 0; f < 4; ++f)
        #pragma unroll
        for (int n = 0; n < 8; ++n)
            #pragma unroll
            for (int e = 0; e < 4; ++e) acc[f][n][e] = 0.f;

    // prologue: stage 0 into buffer 0
    LOAD_X(0, 0); STORE_CHUNK(0,          2 * MAT_H, 0);
    LOAD_X(0, 1); STORE_CHUNK(0,          2 * MAT_H, 1);
    LOAD_C(0, 0); STORE_CHUNK(4 * MAT_H,  6 * MAT_H, 0);
    LOAD_C(0, 1); STORE_CHUNK(4 * MAT_H,  6 * MAT_H, 1);
    __syncthreads();

    for (int g = 0; g < NG; ++g) {
        const int buf = g & 1;
        const int nb  = buf ^ 1;
        const uint32_t AHB = SB + (uint32_t)((0 + buf) * MAT_H) * 2;
        const uint32_t ALB = SB + (uint32_t)((2 + buf) * MAT_H) * 2;
        const uint32_t BHB = SB + (uint32_t)((4 + buf) * MAT_H) * 2;
        const uint32_t BLB = SB + (uint32_t)((6 + buf) * MAT_H) * 2;
        const int ahN = (0 + nb) * MAT_H;
        const int alN = (2 + nb) * MAT_H;
        const int bhN = (4 + nb) * MAT_H;
        const int blN = (6 + nb) * MAT_H;
        const bool pf = (g + 1 < NG);

        if (pf) LOAD_X(g + 1, 0);

        // ================= kk = 0 =================
        {
            uint32_t ah[4][4], bh[4][4];
            #pragma unroll
            for (int f = 0; f < 4; ++f) LDSM4(ah[f], AHB + aBase + f * 1280);
            #pragma unroll
            for (int q = 0; q < 4; ++q) LDSM4(bh[q], BHB + bBase + q * 1280);
            MMA_GROUP(ah, bh);
            if (pf) { STORE_CHUNK(ahN, alN, 0); LOAD_X(g + 1, 1); }
            {
                uint32_t bl[4][4];
                #pragma unroll
                for (int q = 0; q < 4; ++q) LDSM4(bl[q], BLB + bBase + q * 1280);
                MMA_GROUP(ah, bl);
            }
            if (pf) { STORE_CHUNK(ahN, alN, 1); LOAD_C(g + 1, 0); }
            {
                uint32_t al[4][4];
                #pragma unroll
                for (int f = 0; f < 4; ++f) LDSM4(al[f], ALB + aBase + f * 1280);
                MMA_GROUP(al, bh);
            }
            if (pf) { STORE_CHUNK(bhN, blN, 0); LOAD_C(g + 1, 1); }
        }

        // ================= kk = 1 =================
        {
            uint32_t ah[4][4], bh[4][4];
            #pragma unroll
            for (int f = 0; f < 4; ++f) LDSM4(ah[f], AHB + aBase + f * 1280 + 32);
            #pragma unroll
            for (int q = 0; q < 4; ++q) LDSM4(bh[q], BHB + bBase + q * 1280 + 32);
            MMA_GROUP(ah, bh);
            if (pf) STORE_CHUNK(bhN, blN, 1);
            {
                uint32_t bl[4][4];
                #pragma unroll
                for (int q = 0; q < 4; ++q) LDSM4(bl[q], BLB + bBase + q * 1280 + 32);
                MMA_GROUP(ah, bl);
            }
            {
                uint32_t al[4][4];
                #pragma unroll
                for (int f = 0; f < 4; ++f) LDSM4(al[f], ALB + aBase + f * 1280 + 32);
                MMA_GROUP(al, bh);
            }
        }

        // ---- tile epilogue: fold norms, update per-lane argmax ----
        if ((g & 7) == 7) {
            const int cb = (g >> 3) * BN;
            #pragma unroll
            for (int n = 0; n < 8; ++n) {
                #pragma unroll
                for (int e = 0; e < 2; ++e) {
                    const int ci = cb + nbase + 8 * n + 2 * (L & 3) + e;
                    const float hc = -0.5f * dsm[CN_F + ci];
                    #pragma unroll
                    for (int f = 0; f < 4; ++f) {
                        float vlo = acc[f][n][e]     + hc;
                        float vhi = acc[f][n][2 + e] + hc;
                        if (vlo > bV[2 * f])     { bV[2 * f] = vlo;     bI[2 * f] = ci; }
                        if (vhi > bV[2 * f + 1]) { bV[2 * f + 1] = vhi; bI[2 * f + 1] = ci; }
                    }
                }
            }
            if (g + 1 < NG) {
                #pragma unroll
                for (int f = 0; f < 4; ++f)
                    #pragma unroll
                    for (int n = 0; n < 8; ++n)
                        #pragma unroll
                        for (int e = 0; e < 4; ++e) acc[f][n][e] = 0.f;
            }
        }
        __syncthreads();
    }

    // quad reduce (lanes sharing L>>2 cover the same rows)
    #pragma unroll
    for (int i = 0; i < 8; ++i) {
        float v = bV[i]; int idx = bI[i];
        #pragma unroll
        for (int o = 1; o < 4; o <<= 1) {
            float vo = __shfl_xor_sync(0xffffffffu, v, o);
            int   io = __shfl_xor_sync(0xffffffffu, idx, o);
            if (vo > v || (vo == v && io < idx)) { v = vo; idx = io; }
        }
        bV[i] = v; bI[i] = idx;
    }
    if ((L & 3) == 0) {
        const int wn = wid & 1;
        #pragma unroll
        for (int f = 0; f < 4; ++f)
            #pragma unroll
            for (int h = 0; h < 2; ++h) {
                int row = mbase + 16 * f + 8 * h + (L >> 2);
                sV[wn][row] = bV[2 * f + h];
                sI[wn][row] = bI[2 * f + h];
            }
    }
    __syncthreads();

    // combine the two n-warps, publish winners
    {
        float v0 = sV[0][tid], v1 = sV[1][tid];
        int   i0 = sI[0][tid], i1 = sI[1][tid];
        int idx = (v1 > v0 || (v1 == v0 && i1 < i0)) ? i1 : i0;
        bidx_s[tid] = idx;
        out[OUT_IDX + rowBase + tid] = (float)idx;
    }
    __syncthreads();

    // gather codes, write z_q_x and z_q_x_bar
    const float4* emb4 = (const float4*)emb;
    float4* o4 = (float4*)out;
    #pragma unroll 4
    for (int it = 0; it < 64; ++it) {
        int gg = tid + it * 128;         // 0..8191
        int m = gg >> 6;                 // 0..127
        int q = gg & 63;
        int code = bidx_s[m];
        float4 v = emb4[(size_t)code * 64 + q];
        size_t off = (size_t)(rowBase + m) * 64 + q;
        o4[off] = v;
        o4[off + (OUT_BAR / 4)] = v;
    }
}

// ---------------------------------------------------------------------------
extern "C" void kernel_launch(void* const* d_in, const int* in_sizes, int n_in,
                              void* d_out, int out_size) {
    const float* x   = (const float*)d_in[0];
    const float* emb = (const float*)d_in[1];
    float* out = (float*)d_out;

    cudaFuncSetAttribute(vq_mma_kernel, cudaFuncAttributeMaxDynamicSharedMemorySize, DYN_SMEM);

    cnorm_kernel<<<KCODE / 8, 256>>>(emb);
    vq_mma_kernel<<<NTOK / BM, 128, DYN_SMEM>>>(x, emb, out);
}

// round 13
// speedup vs baseline: 1.3025x; 1.3025x over previous
#include <cuda_runtime.h>
#include <cuda_fp16.h>
#include <cstdint>

// VQ nearest-codebook lookup via 3-term FP16 mma.sync distance GEMM.
// R13: R6's proven double-buffered pipeline shape (BM=256, 64x64 warp tiles,
// 8 warps, split-at-store, interleaved LDG/STS between mma groups) with fp16
// m16n8k16 (half the mma instructions of tf32 k8 at equal per-instr cost).
//   z_e_x: [16,2048,256] f32 -> N=32768 rows, D=256
//   embedding: [1024,256] f32 -> K=1024 codes
// d_out (f32): z_q_x [N*D] @0, z_q_x_bar [N*D] @8388608, indices [N] @16777216
// argmax_k(x.c - ||c||^2/2); x = xh + xl (fp16 split), keep hh + hl + lh.

#define NTOK   32768
#define DDIM   256
#define KCODE  1024
#define BM     256
#define BN     128
#define KS     32              // k per stage (two k16 chunks)
#define NTILE  8
#define NG     64              // NTILE * (DDIM/KS)
#define PITCHH 40              // halves per row (80B pitch, ldsm conflict-free)

#define OUT_BAR   8388608
#define OUT_IDX  16777216

// half-index layout
#define MATA_H (BM * PITCHH)         // 10240 halves per A matrix-stage
#define MATB_H (BN * PITCHH)         // 5120 halves per B matrix-stage
#define AH_H   0                     // 2 bufs
#define AL_H   (2 * MATA_H)          // 20480
#define BH_H   (4 * MATA_H)          // 40960, 2 bufs
#define BL_H   (BH_H + 2 * MATB_H)   // 51200
#define END_H  (BL_H + 2 * MATB_H)   // 61440
#define CN_F   (END_H / 2)           // 30720 (float index)
#define DYN_SMEM (END_H * 2 + KCODE * 4)   // 126976 B

__device__ float g_cnorm[KCODE];

// ---------------------------------------------------------------------------
__device__ __forceinline__ uint32_t smem_u32(const void* p) {
    uint32_t a;
    asm("{ .reg .u64 t; cvta.to.shared.u64 t, %1; cvt.u32.u64 %0, t; }"
        : "=r"(a) : "l"(p));
    return a;
}
#define LDSM4(r, addr) \
    asm volatile("ldmatrix.sync.aligned.m8n8.x4.shared.b16 {%0,%1,%2,%3}, [%4];" \
        : "=r"((r)[0]), "=r"((r)[1]), "=r"((r)[2]), "=r"((r)[3]) : "r"(addr))

__device__ __forceinline__ void mma_f16(float* c, const uint32_t* a,
                                        uint32_t b0, uint32_t b1) {
    asm volatile(
        "mma.sync.aligned.m16n8k16.row.col.f32.f16.f16.f32 "
        "{%0,%1,%2,%3}, {%4,%5,%6,%7}, {%8,%9}, {%0,%1,%2,%3};"
        : "+f"(c[0]), "+f"(c[1]), "+f"(c[2]), "+f"(c[3])
        : "r"(a[0]), "r"(a[1]), "r"(a[2]), "r"(a[3]), "r"(b0), "r"(b1));
}

__device__ __forceinline__ uint32_t h2u(__half2 v) {
    return *reinterpret_cast<uint32_t*>(&v);
}

__device__ __forceinline__ void split_f4(float4 v, uint2& h, uint2& l) {
    __half2 h01 = __floats2half2_rn(v.x, v.y);
    __half2 h23 = __floats2half2_rn(v.z, v.w);
    float2 f01 = __half22float2(h01);
    float2 f23 = __half22float2(h23);
    __half2 l01 = __floats2half2_rn(v.x - f01.x, v.y - f01.y);
    __half2 l23 = __floats2half2_rn(v.z - f23.x, v.w - f23.y);
    h.x = h2u(h01); h.y = h2u(h23);
    l.x = h2u(l01); l.y = h2u(l23);
}

// ---------------------------------------------------------------------------
__global__ void cnorm_kernel(const float* __restrict__ emb) {
    int warp = (blockIdx.x * blockDim.x + threadIdx.x) >> 5;
    int lane = threadIdx.x & 31;
    if (warp >= KCODE) return;
    const float* row = emb + (size_t)warp * DDIM;
    float s = 0.f;
    #pragma unroll
    for (int k = lane; k < DDIM; k += 32) { float v = row[k]; s += v * v; }
    #pragma unroll
    for (int o = 16; o; o >>= 1) s += __shfl_xor_sync(0xffffffffu, s, o);
    if (lane == 0) g_cnorm[warp] = s;
}

// ---------------------------------------------------------------------------
// 256 threads = 8 warps in 4(m) x 2(n); warp tile 64 rows x 64 codes.
// ---------------------------------------------------------------------------
__global__ __launch_bounds__(256, 1)
void vq_mma_kernel(const float* __restrict__ x,
                   const float* __restrict__ emb,
                   float* __restrict__ out) {
    extern __shared__ float dsm[];
    __half* hsm = (__half*)dsm;
    __shared__ float sV[2][BM];
    __shared__ int   sI[2][BM];
    __shared__ int   bidx_s[BM];

    const int tid = threadIdx.x;
    const int wid = tid >> 5;
    const int L   = tid & 31;
    const int rowBase = blockIdx.x * BM;
    const int mbase = (wid >> 1) * 64;       // 0/64/128/192
    const int nbase = (wid & 1) * 64;        // 0/64

    const uint32_t SB = smem_u32(dsm);

    // ldmatrix lane geometry (byte offsets inside a matrix-stage; 80B pitch)
    const int aRow = (L & 7) + 8 * ((L >> 3) & 1);
    const int aK   = (L >> 4) * 16;
    const uint32_t aBase = (uint32_t)((mbase + aRow) * 80 + aK);
    const uint32_t bBase = (uint32_t)((nbase + aRow) * 80 + aK);

    // loader geometry: row lRow (+64i), float4 slot lKg within a 16-float chunk
    const int lRow = tid >> 2;          // 0..63
    const int lKg  = tid & 3;

    // cnorm table into smem (once)
    #pragma unroll
    for (int i = 0; i < 4; ++i) dsm[CN_F + tid + 256 * i] = g_cnorm[tid + 256 * i];

    float bV[8];
    int   bI[8];
    #pragma unroll
    for (int i = 0; i < 8; ++i) { bV[i] = -3.4e38f; bI[i] = 0x7fffffff; }

    float4 vS[4];

    // ---- A: rows lRow+64i (i=0..3), one 16-float chunk c of stage sidx ----
    #define LOAD_A(sidx, c) do { \
        const float* _p = x + (size_t)(rowBase + lRow) * DDIM \
                        + ((sidx) & 7) * KS + (c) * 16 + lKg * 4; \
        vS[0] = *(const float4*)(_p); \
        vS[1] = *(const float4*)(_p +  64 * DDIM); \
        vS[2] = *(const float4*)(_p + 128 * DDIM); \
        vS[3] = *(const float4*)(_p + 192 * DDIM); \
    } while (0)

    #define STORE_A(nb, c) do { \
        _Pragma("unroll") \
        for (int _i = 0; _i < 4; ++_i) { \
            uint2 _h, _l; \
            split_f4(vS[_i], _h, _l); \
            const int _o = (lRow + 64 * _i) * PITCHH + (c) * 16 + lKg * 4; \
            *(uint2*)&hsm[AH_H + (nb) * MATA_H + _o] = _h; \
            *(uint2*)&hsm[AL_H + (nb) * MATA_H + _o] = _l; \
        } \
    } while (0)

    // ---- B: rows lRow+64i (i=0..1), chunk c ----
    #define LOAD_B(sidx, c) do { \
        const float* _p = emb + (size_t)(((sidx) >> 3) * BN + lRow) * DDIM \
                        + ((sidx) & 7) * KS + (c) * 16 + lKg * 4; \
        vS[0] = *(const float4*)(_p); \
        vS[1] = *(const float4*)(_p + 64 * DDIM); \
    } while (0)

    #define STORE_B(nb, c) do { \
        _Pragma("unroll") \
        for (int _i = 0; _i < 2; ++_i) { \
            uint2 _h, _l; \
            split_f4(vS[_i], _h, _l); \
            const int _o = (lRow + 64 * _i) * PITCHH + (c) * 16 + lKg * 4; \
            *(uint2*)&hsm[BH_H + (nb) * MATB_H + _o] = _h; \
            *(uint2*)&hsm[BL_H + (nb) * MATB_H + _o] = _l; \
        } \
    } while (0)

    #define MMA_GROUP(afr, bfr) do { \
        _Pragma("unroll") \
        for (int _f = 0; _f < 4; ++_f) \
            _Pragma("unroll") \
            for (int _q = 0; _q < 4; ++_q) { \
                mma_f16(acc[_f][2 * _q],     (afr)[_f], (bfr)[_q][0], (bfr)[_q][2]); \
                mma_f16(acc[_f][2 * _q + 1], (afr)[_f], (bfr)[_q][1], (bfr)[_q][3]); \
            } \
    } while (0)

    float acc[4][8][4];
    #pragma unroll
    for (int f = 0; f < 4; ++f)
        #pragma unroll
        for (int n = 0; n < 8; ++n)
            #pragma unroll
            for (int e = 0; e < 4; ++e) acc[f][n][e] = 0.f;

    // prologue: stage 0 into buffer 0
    LOAD_A(0, 0); STORE_A(0, 0);
    LOAD_A(0, 1); STORE_A(0, 1);
    LOAD_B(0, 0); STORE_B(0, 0);
    LOAD_B(0, 1); STORE_B(0, 1);
    __syncthreads();

    for (int g = 0; g < NG; ++g) {
        const int buf = g & 1;
        const int nb  = buf ^ 1;
        const uint32_t AHB = SB + (uint32_t)(AH_H + buf * MATA_H) * 2;
        const uint32_t ALB = SB + (uint32_t)(AL_H + buf * MATA_H) * 2;
        const uint32_t BHB = SB + (uint32_t)(BH_H + buf * MATB_H) * 2;
        const uint32_t BLB = SB + (uint32_t)(BL_H + buf * MATB_H) * 2;
        const bool pf = (g + 1 < NG);

        if (pf) LOAD_A(g + 1, 0);

        // ================= kk = 0 =================
        {
            uint32_t ah[4][4], bh[4][4];
            #pragma unroll
            for (int f = 0; f < 4; ++f) LDSM4(ah[f], AHB + aBase + f * 1280);
            #pragma unroll
            for (int q = 0; q < 4; ++q) LDSM4(bh[q], BHB + bBase + q * 1280);
            MMA_GROUP(ah, bh);
            if (pf) { STORE_A(nb, 0); LOAD_A(g + 1, 1); }
            {
                uint32_t bl[4][4];
                #pragma unroll
                for (int q = 0; q < 4; ++q) LDSM4(bl[q], BLB + bBase + q * 1280);
                MMA_GROUP(ah, bl);
            }
            if (pf) { STORE_A(nb, 1); LOAD_B(g + 1, 0); }
            {
                uint32_t al[4][4];
                #pragma unroll
                for (int f = 0; f < 4; ++f) LDSM4(al[f], ALB + aBase + f * 1280);
                MMA_GROUP(al, bh);
            }
            if (pf) { STORE_B(nb, 0); LOAD_B(g + 1, 1); }
        }

        // ================= kk = 1 =================
        {
            uint32_t ah[4][4], bh[4][4];
            #pragma unroll
            for (int f = 0; f < 4; ++f) LDSM4(ah[f], AHB + aBase + f * 1280 + 32);
            #pragma unroll
            for (int q = 0; q < 4; ++q) LDSM4(bh[q], BHB + bBase + q * 1280 + 32);
            MMA_GROUP(ah, bh);
            if (pf) STORE_B(nb, 1);
            {
                uint32_t bl[4][4];
                #pragma unroll
                for (int q = 0; q < 4; ++q) LDSM4(bl[q], BLB + bBase + q * 1280 + 32);
                MMA_GROUP(ah, bl);
            }
            {
                uint32_t al[4][4];
                #pragma unroll
                for (int f = 0; f < 4; ++f) LDSM4(al[f], ALB + aBase + f * 1280 + 32);
                MMA_GROUP(al, bh);
            }
        }

        // ---- tile epilogue: fold norms, update per-lane argmax ----
        if ((g & 7) == 7) {
            const int cb = (g >> 3) * BN;
            #pragma unroll
            for (int n = 0; n < 8; ++n) {
                #pragma unroll
                for (int e = 0; e < 2; ++e) {
                    const int ci = cb + nbase + 8 * n + 2 * (L & 3) + e;
                    const float hc = -0.5f * dsm[CN_F + ci];
                    #pragma unroll
                    for (int f = 0; f < 4; ++f) {
                        float vlo = acc[f][n][e]     + hc;
                        float vhi = acc[f][n][2 + e] + hc;
                        if (vlo > bV[2 * f])     { bV[2 * f] = vlo;     bI[2 * f] = ci; }
                        if (vhi > bV[2 * f + 1]) { bV[2 * f + 1] = vhi; bI[2 * f + 1] = ci; }
                    }
                }
            }
            if (g + 1 < NG) {
                #pragma unroll
                for (int f = 0; f < 4; ++f)
                    #pragma unroll
                    for (int n = 0; n < 8; ++n)
                        #pragma unroll
                        for (int e = 0; e < 4; ++e) acc[f][n][e] = 0.f;
            }
        }
        __syncthreads();
    }

    // quad reduce (lanes sharing L>>2 cover the same rows)
    #pragma unroll
    for (int i = 0; i < 8; ++i) {
        float v = bV[i]; int idx = bI[i];
        #pragma unroll
        for (int o = 1; o < 4; o <<= 1) {
            float vo = __shfl_xor_sync(0xffffffffu, v, o);
            int   io = __shfl_xor_sync(0xffffffffu, idx, o);
            if (vo > v || (vo == v && io < idx)) { v = vo; idx = io; }
        }
        bV[i] = v; bI[i] = idx;
    }
    if ((L & 3) == 0) {
        const int wn = wid & 1;
        #pragma unroll
        for (int f = 0; f < 4; ++f)
            #pragma unroll
            for (int h = 0; h < 2; ++h) {
                int row = mbase + 16 * f + 8 * h + (L >> 2);
                sV[wn][row] = bV[2 * f + h];
                sI[wn][row] = bI[2 * f + h];
            }
    }
    __syncthreads();

    // combine the two n-warps, publish winners
    {
        float v0 = sV[0][tid], v1 = sV[1][tid];
        int   i0 = sI[0][tid], i1 = sI[1][tid];
        int idx = (v1 > v0 || (v1 == v0 && i1 < i0)) ? i1 : i0;
        bidx_s[tid] = idx;
        out[OUT_IDX + rowBase + tid] = (float)idx;
    }
    __syncthreads();

    // gather codes, write z_q_x and z_q_x_bar
    const float4* emb4 = (const float4*)emb;
    float4* o4 = (float4*)out;
    #pragma unroll 4
    for (int it = 0; it < 64; ++it) {
        int gg = tid + it * 256;         // 0..16383
        int m = gg >> 6;                 // 0..255
        int q = gg & 63;
        int code = bidx_s[m];
        float4 v = emb4[(size_t)code * 64 + q];
        size_t off = (size_t)(rowBase + m) * 64 + q;
        o4[off] = v;
        o4[off + (OUT_BAR / 4)] = v;
    }
}

// ---------------------------------------------------------------------------
extern "C" void kernel_launch(void* const* d_in, const int* in_sizes, int n_in,
                              void* d_out, int out_size) {
    const float* x   = (const float*)d_in[0];
    const float* emb = (const float*)d_in[1];
    float* out = (float*)d_out;

    cudaFuncSetAttribute(vq_mma_kernel, cudaFuncAttributeMaxDynamicSharedMemorySize, DYN_SMEM);

    cnorm_kernel<<<KCODE / 8, 256>>>(emb);
    vq_mma_kernel<<<NTOK / BM, 256, DYN_SMEM>>>(x, emb, out);
}